// round 14
// baseline (speedup 1.0000x reference)
#include <cuda_runtime.h>
#include <cstdint>

#define NB  32
#define ND  128
#define NCL 1024
#define NQL 512

// ---------------- scratch (device globals: allocation-free) ----------------
__device__ float g_Aeff[(size_t)NB * NCL * ND];     // Aeff[b][c][d]
__device__ float g_bias[(size_t)NB * NCL];          // bias[b][c]
__device__ float g_E2 [(size_t)NB * NCL * NQL];     // exp(S+bias)  [b][c][q]
__device__ float g_Lp [(size_t)NB * 8 * NQL];       // column partial sums
__device__ float g_Rp [(size_t)NB * 4 * NCL];       // row partial sums
__device__ float g_invl[(size_t)NB * NQL];          // 1 / column sum
__device__ float g_rinv[(size_t)NB * NCL];          // 1 / row sum
__device__ float g_T  [(size_t)NB * ND * NQL];      // T[b][d][q] = S2tC^T

// ---------------- helpers ---------------------------------------------------
__device__ __forceinline__ void mma8(float* d, const uint32_t* a, const uint32_t* b) {
    asm("mma.sync.aligned.m16n8k8.row.col.f32.tf32.tf32.f32 "
        "{%0,%1,%2,%3}, {%4,%5,%6,%7}, {%8,%9}, {%0,%1,%2,%3};"
        : "+f"(d[0]), "+f"(d[1]), "+f"(d[2]), "+f"(d[3])
        : "r"(a[0]), "r"(a[1]), "r"(a[2]), "r"(a[3]), "r"(b[0]), "r"(b[1]));
}
__device__ __forceinline__ uint4 ldsm4(uint32_t addr) {
    uint4 r;
    asm volatile("ldmatrix.sync.aligned.m8n8.x4.shared.b16 {%0,%1,%2,%3}, [%4];"
                 : "=r"(r.x), "=r"(r.y), "=r"(r.z), "=r"(r.w) : "r"(addr));
    return r;
}
#define CP16(dst, src) \
    asm volatile("cp.async.cg.shared.global [%0], [%1], 16;" :: "r"(dst), "l"(src))
#define CPCOMMIT() asm volatile("cp.async.commit_group;" ::)
#define CPWAIT2()  asm volatile("cp.async.wait_group 2;" ::: "memory")

// ---------------- K0: Aeff = wq + wqc*Ct ; bias = wc . Ct ; out[sec0]=C -----
__global__ __launch_bounds__(256) void prep_kernel(
    const float* __restrict__ C, const float* __restrict__ W,
    float* __restrict__ Aeff, float* __restrict__ bias,
    float* __restrict__ out)
{
    __shared__ float Csm[ND][33];
    const int b  = blockIdx.y;
    const int c0 = blockIdx.x * 32;
    const int t  = threadIdx.x;
    const float* Cb = C + (size_t)b * ND * NCL;
    float* Ob = out + (size_t)b * 4 * ND * NCL;

    #pragma unroll
    for (int i = 0; i < 16; i++) {
        int idx = i * 256 + t;
        int d = idx >> 5, c = idx & 31;
        float v = Cb[(size_t)d * NCL + c0 + c];
        Csm[d][c] = v;
        Ob[(size_t)d * NCL + c0 + c] = v;   // out section 0 = C
    }
    __syncthreads();

    #pragma unroll
    for (int i = 0; i < 16; i++) {
        int idx = i * 256 + t;
        int c = idx >> 7, d = idx & 127;
        size_t wb = (size_t)(b * NCL + c0 + c) * 384;
        float wq  = W[wb + d];
        float wqc = W[wb + 256 + d];
        Aeff[(size_t)(b * NCL + c0 + c) * ND + d] = wq + wqc * Csm[d][c];
    }

    int w = t >> 5, lane = t & 31;
    #pragma unroll
    for (int j = 0; j < 4; j++) {
        int c = w + j * 8;
        size_t wb = (size_t)(b * NCL + c0 + c) * 384 + 128;
        float s = 0.f;
        #pragma unroll
        for (int jj = 0; jj < 4; jj++) {
            int d = lane + jj * 32;
            s += W[wb + d] * Csm[d][c];
        }
        #pragma unroll
        for (int off = 16; off; off >>= 1)
            s += __shfl_xor_sync(0xffffffffu, s, off);
        if (lane == 0) bias[b * NCL + c0 + c] = s;
    }
}

// ---------------- tf32 tensor-core GEMM: cp.async + ldmatrix pipeline --------
// 4-stage cp.async ring (3 tiles in flight), dynamic smem, swizzled tiles.
// Warp grid: WM (m) x 8/WM (n).  MI = m-atoms/warp, NI = n-atoms/warp.
// EPI=1: store exp(acc+bias[m]) + col/row partial sums (K1).
// EPI=2 & !MERGE: C = acc * xtra1[col]  (K4 -> T).
// EPI=2 & MERGE : fused final assembly (ysel=0 -> sec1,sec2 ; ysel=1 -> sec3).
template <bool TRANSB, int EPI, int BN, bool MERGE, int WM, int OCC>
__global__ __launch_bounds__(256, OCC) void mma_gemm(
    const float* __restrict__ Aall, const float* __restrict__ Aall2,
    const float* __restrict__ Ball,
    float* __restrict__ Call, const float* __restrict__ Cprod,
    int M, int N, int K,
    size_t aStride, size_t bStride, size_t cStride,
    const float* __restrict__ xtra1,
    float* __restrict__ colpart, float* __restrict__ rowpart,
    int ysel)
{
    constexpr int BM = 128, BK = 16, STG = 4;
    constexpr int WN = 8 / WM;
    constexpr int MI = BM / (16 * WM);
    constexpr int NI = BN / (8 * WN);
    constexpr int ABYTES = BM * BK * 4;   // 8192
    constexpr int BBYTES = BK * BN * 4;   // 8192 / 4096

    extern __shared__ float sdyn[];
    float* As = sdyn;                          // STG * BM*BK
    float* Bs = sdyn + STG * BM * BK;          // STG * BK*BN

    const int b  = blockIdx.z;
    const int n0 = blockIdx.x * BN;
    const int m0 = MERGE ? 0 : blockIdx.y * BM;
    const float* Abase = MERGE ? (ysel ? Aall2 : Aall) : Aall;
    const float* A  = Abase + (size_t)b * aStride + (size_t)m0 * K;
    const float* Bp = Ball + (size_t)b * bStride;
    float*       Cm = Call + (size_t)b * cStride;

    const int tid  = threadIdx.x;
    const int w    = tid >> 5;
    const int lane = tid & 31;
    const int g    = lane >> 2;
    const int t    = lane & 3;
    const int wq   = w / WN;                 // m-warp index
    const int wr   = w % WN;                 // n-warp index
    const int wm   = wq * (16 * MI);
    const int wn   = wr * (8 * NI);
    const int na0  = wr * NI;

    const uint32_t sAu = (uint32_t)__cvta_generic_to_shared(As);
    const uint32_t sBu = (uint32_t)__cvta_generic_to_shared(Bs);
    const int T = K / BK;

    // ---- global->smem loader setup (16B chunks, swizzled dst) ----
    const int rA = tid >> 2, cA = tid & 3;
    const float* gA0 = A + (size_t)rA * K + cA * 4;
    const float* gA1 = gA0 + (size_t)64 * K;
    const uint32_t dA0 = sAu + ((rA * 4 + (cA ^ ((rA >> 1) & 3))) << 4);
    const uint32_t dA1 = dA0 + 4096;

    const float* gB0;
    const float* gB1 = nullptr;
    uint32_t dB0, dB1 = 0;
    if (TRANSB) {
        const int rB = tid >> 2, cB = tid & 3;
        gB0 = Bp + (size_t)(n0 + rB) * K + cB * 4;
        dB0 = sBu + ((rB * 4 + (cB ^ ((rB >> 1) & 3))) << 4);
        if (BN == 128) { gB1 = gB0 + (size_t)64 * K; dB1 = dB0 + 4096; }
    } else {
        const int kB = tid >> 4, cB = tid & 15;
        gB0 = Bp + (size_t)kB * N + n0 + cB * 4;
        dB0 = sBu + ((kB * (BN / 4) + (cB ^ (2 * (kB & 3)))) << 4);
        if (BN == 128) { gB1 = gB0 + 64; dB1 = dB0 + 256; }
    }

    auto issue_tile = [&](int stage) {
        const uint32_t ao = stage * ABYTES, bo = stage * BBYTES;
        CP16(dA0 + ao, gA0); CP16(dA1 + ao, gA1);
        gA0 += BK; gA1 += BK;
        CP16(dB0 + bo, gB0);
        if (BN == 128) CP16(dB1 + bo, gB1);
        if (TRANSB) { gB0 += BK; if (BN == 128) gB1 += BK; }
        else        { gB0 += (size_t)BK * N; if (BN == 128) gB1 += (size_t)BK * N; }
    };

    // ---- fragment address precompute ----
    const int aRow = wm + ((lane >> 3) & 1) * 8 + (lane & 7);
    const int aSel = lane >> 4;
    const int fSwz = (lane >> 1) & 3;
    const int aB0  = aRow * 64;
    const int ax[2] = { ((aSel) ^ fSwz) << 4, ((2 + aSel) ^ fSwz) << 4 };

    int bRB[TRANSB ? (NI / 2) : 1];
    int bx0 = 0, bx1 = 0;
    if (TRANSB) {
        const int bSel = (lane >> 3) & 1;
        bx0 = ((bSel) ^ fSwz) << 4;
        bx1 = ((2 + bSel) ^ fSwz) << 4;
        #pragma unroll
        for (int p = 0; p < NI / 2; p++)
            bRB[p] = ((na0 + 2 * p + (lane >> 4)) * 8 + (lane & 7)) * 64;
    }
    int colB[TRANSB ? 1 : NI];
    int rw0 = 0, rw1 = 0;
    if (!TRANSB) {
        #pragma unroll
        for (int in = 0; in < NI; in++) {
            int cn = (wn >> 2) + in * 2 + (g >> 2);
            colB[in] = ((cn ^ (2 * t)) << 2) + (g & 3);
        }
        rw0 = t * BN;
        rw1 = (8 + t) * BN;
    }

    float acc[MI][NI][4];
    #pragma unroll
    for (int i = 0; i < MI; i++)
        #pragma unroll
        for (int j = 0; j < NI; j++)
            #pragma unroll
            for (int r = 0; r < 4; r++) acc[i][j][r] = 0.f;

    // ---- prologue: 3 stages in flight ----
    issue_tile(0); CPCOMMIT();
    issue_tile(1); CPCOMMIT();
    issue_tile(2); CPCOMMIT();

    for (int it = 0; it < T; ++it) {
        CPWAIT2();
        __syncthreads();
        if (it + 3 < T) issue_tile((it + 3) % STG);
        CPCOMMIT();

        const int st = it % STG;
        const uint32_t aSt = sAu + st * ABYTES;
        const uint32_t bSt = sBu + st * BBYTES;
        const uint32_t* Bw = (const uint32_t*)(Bs + st * BK * BN);

        #pragma unroll
        for (int ks = 0; ks < 2; ks++) {
            uint4 af[MI];
            #pragma unroll
            for (int im = 0; im < MI; im++)
                af[im] = ldsm4(aSt + aB0 + im * 1024 + ax[ks]);

            uint32_t bf[NI][2];
            if (TRANSB) {
                #pragma unroll
                for (int p = 0; p < NI / 2; p++) {
                    uint4 bv = ldsm4(bSt + bRB[p] + (ks ? bx1 : bx0));
                    bf[2 * p][0] = bv.x; bf[2 * p][1] = bv.y;
                    bf[2 * p + 1][0] = bv.z; bf[2 * p + 1][1] = bv.w;
                }
            } else {
                const int rw = ks ? rw1 : rw0;
                #pragma unroll
                for (int in = 0; in < NI; in++) {
                    bf[in][0] = Bw[rw + colB[in]];
                    bf[in][1] = Bw[rw + colB[in] + 4 * BN];
                }
            }
            #pragma unroll
            for (int im = 0; im < MI; im++)
                #pragma unroll
                for (int in = 0; in < NI; in++)
                    mma8(acc[im][in], (const uint32_t*)&af[im], bf[in]);
        }
    }

    // ---------------- epilogue ----------------
    if constexpr (EPI == 1) {
        float bias_r[MI][2];
        #pragma unroll
        for (int im = 0; im < MI; im++)
            #pragma unroll
            for (int h = 0; h < 2; h++)
                bias_r[im][h] = xtra1[(size_t)b * M + m0 + wm + im * 16 + g + 8 * h];

        float qs[NI][2];
        float rs[MI][2];
        #pragma unroll
        for (int i = 0; i < NI; i++) { qs[i][0] = 0.f; qs[i][1] = 0.f; }
        #pragma unroll
        for (int i = 0; i < MI; i++) { rs[i][0] = 0.f; rs[i][1] = 0.f; }

        #pragma unroll
        for (int im = 0; im < MI; im++)
            #pragma unroll
            for (int h = 0; h < 2; h++) {
                int m = m0 + wm + im * 16 + g + 8 * h;
                #pragma unroll
                for (int in = 0; in < NI; in++) {
                    float e0 = __expf(acc[im][in][2 * h]     + bias_r[im][h]);
                    float e1 = __expf(acc[im][in][2 * h + 1] + bias_r[im][h]);
                    float2 v; v.x = e0; v.y = e1;
                    *(float2*)&Cm[(size_t)m * N + n0 + wn + in * 8 + 2 * t] = v;
                    qs[in][0] += e0; qs[in][1] += e1;
                    rs[im][h] += e0 + e1;
                }
            }
        __syncthreads();
        float* red_c = sdyn;                 // [WM][BN]
        float* red_r = sdyn + WM * BN;       // [WN][BM]
        #pragma unroll
        for (int in = 0; in < NI; in++)
            #pragma unroll
            for (int j = 0; j < 2; j++) {
                float s = qs[in][j];
                s += __shfl_xor_sync(0xffffffffu, s, 16);
                s += __shfl_xor_sync(0xffffffffu, s, 8);
                s += __shfl_xor_sync(0xffffffffu, s, 4);
                if (g == 0) red_c[wq * BN + wn + in * 8 + 2 * t + j] = s;
            }
        #pragma unroll
        for (int im = 0; im < MI; im++)
            #pragma unroll
            for (int h = 0; h < 2; h++) {
                float s = rs[im][h];
                s += __shfl_xor_sync(0xffffffffu, s, 1);
                s += __shfl_xor_sync(0xffffffffu, s, 2);
                if (t == 0) red_r[wr * BM + wm + im * 16 + g + 8 * h] = s;
            }
        __syncthreads();
        if (tid < BN) {
            float s = 0.f;
            #pragma unroll
            for (int k2 = 0; k2 < WM; k2++) s += red_c[k2 * BN + tid];
            colpart[((size_t)b * gridDim.y + blockIdx.y) * N + n0 + tid] = s;
        } else if (tid < BN + BM) {
            int m = tid - BN;
            float s = 0.f;
            #pragma unroll
            for (int k2 = 0; k2 < WN; k2++) s += red_r[k2 * BM + m];
            rowpart[((size_t)b * gridDim.x + blockIdx.x) * M + m0 + m] = s;
        }
    } else {
        float sc[NI][2];
        #pragma unroll
        for (int in = 0; in < NI; in++)
            #pragma unroll
            for (int j = 0; j < 2; j++)
                sc[in][j] = xtra1[(size_t)b * N + n0 + wn + in * 8 + 2 * t + j];

        if constexpr (MERGE) {
            // fused assembly: Cm = out + b*4*ND*NCL
            const float* Cin = Cprod + (size_t)b * ND * NCL;
            #pragma unroll
            for (int im = 0; im < MI; im++)
                #pragma unroll
                for (int h = 0; h < 2; h++) {
                    int m = wm + im * 16 + g + 8 * h;
                    #pragma unroll
                    for (int in = 0; in < NI; in++) {
                        int col = n0 + wn + in * 8 + 2 * t;
                        float2 v;
                        v.x = acc[im][in][2 * h]     * sc[in][0];
                        v.y = acc[im][in][2 * h + 1] * sc[in][1];
                        float2 cv = *(const float2*)&Cin[(size_t)m * NCL + col];
                        float2 p; p.x = cv.x * v.x; p.y = cv.y * v.y;
                        if (ysel == 0) {
                            *(float2*)&Cm[(size_t)(ND + m) * NCL + col] = v;
                            *(float2*)&Cm[(size_t)(2 * ND + m) * NCL + col] = p;
                        } else {
                            *(float2*)&Cm[(size_t)(3 * ND + m) * NCL + col] = p;
                        }
                    }
                }
        } else {
            #pragma unroll
            for (int im = 0; im < MI; im++)
                #pragma unroll
                for (int h = 0; h < 2; h++) {
                    int m = m0 + wm + im * 16 + g + 8 * h;
                    #pragma unroll
                    for (int in = 0; in < NI; in++) {
                        float2 v;
                        v.x = acc[im][in][2 * h]     * sc[in][0];
                        v.y = acc[im][in][2 * h + 1] * sc[in][1];
                        *(float2*)&Cm[(size_t)m * N + n0 + wn + in * 8 + 2 * t] = v;
                    }
                }
        }
    }
}

// ---------------- combine partial sums -> invl (per q), rinv (per c) --------
__global__ __launch_bounds__(256) void combine_k(
    const float* __restrict__ Lp, const float* __restrict__ Rp,
    float* __restrict__ invl, float* __restrict__ rinv)
{
    int i = blockIdx.x * 256 + threadIdx.x;
    const int nbq = NB * NQL;
    if (i < nbq) {
        int b = i >> 9, q = i & 511;
        float s = 0.f;
        #pragma unroll
        for (int y = 0; y < 8; y++) s += Lp[((size_t)b * 8 + y) * NQL + q];
        invl[i] = 1.f / s;
    } else {
        int j = i - nbq;
        int b = j >> 10, c = j & 1023;
        float s = 0.f;
        #pragma unroll
        for (int x = 0; x < 4; x++) s += Rp[((size_t)b * 4 + x) * NCL + c];
        rinv[j] = 1.f / s;
    }
}

// ---------------- launch ----------------------------------------------------
extern "C" void kernel_launch(void* const* d_in, const int* in_sizes, int n_in,
                              void* d_out, int out_size)
{
    const float* C = (const float*)d_in[0];   // (B, D, CL)
    const float* Q = (const float*)d_in[1];   // (B, D, QL)
    const float* W = (const float*)d_in[2];   // (B*CL, 1, 3D)
    float* out = (float*)d_out;               // (B, 4D, CL)

    float *pAeff, *pbias, *pE2, *pLp, *pRp, *pinvl, *prinv, *pT;
    cudaGetSymbolAddress((void**)&pAeff, g_Aeff);
    cudaGetSymbolAddress((void**)&pbias, g_bias);
    cudaGetSymbolAddress((void**)&pE2,   g_E2);
    cudaGetSymbolAddress((void**)&pLp,   g_Lp);
    cudaGetSymbolAddress((void**)&pRp,   g_Rp);
    cudaGetSymbolAddress((void**)&pinvl, g_invl);
    cudaGetSymbolAddress((void**)&prinv, g_rinv);
    cudaGetSymbolAddress((void**)&pT,    g_T);

    // one-time side stream + events (host objects, no device allocation)
    static cudaStream_t s2 = nullptr;
    static cudaEvent_t evF = nullptr, evJ = nullptr;
    if (!s2) {
        cudaStreamCreateWithFlags(&s2, cudaStreamNonBlocking);
        cudaEventCreateWithFlags(&evF, cudaEventDisableTiming);
        cudaEventCreateWithFlags(&evJ, cudaEventDisableTiming);
    }

    // dynamic smem sizes: STG=4 stages of (A 8KB + B 8KB/4KB)
    const int SM128 = 4 * (8192 + 8192);   // 64 KB
    const int SM64  = 4 * (8192 + 4096);   // 48 KB
    cudaFuncSetAttribute(mma_gemm<false, 1, 128, false, 2, 2>,
                         cudaFuncAttributeMaxDynamicSharedMemorySize, SM128);
    cudaFuncSetAttribute(mma_gemm<false, 2, 64, false, 4, 3>,
                         cudaFuncAttributeMaxDynamicSharedMemorySize, SM64);
    cudaFuncSetAttribute(mma_gemm<true, 2, 128, true, 2, 2>,
                         cudaFuncAttributeMaxDynamicSharedMemorySize, SM128);

    // K0: Aeff + bias + out[sec0] = C
    prep_kernel<<<dim3(NCL / 32, NB), 256>>>(C, W, pAeff, pbias, out);

    // K1: E2 = exp(Aeff @ Q + bias[c]); column+row partial sums
    mma_gemm<false, 1, 128, false, 2, 2><<<dim3(NQL / 128, NCL / 128, NB), 256, SM128>>>(
        pAeff, nullptr, Q, pE2, nullptr, NCL, NQL, ND,
        (size_t)NCL * ND, (size_t)ND * NQL, (size_t)NCL * NQL,
        pbias, pLp, pRp, 0);

    // combine -> invl[b][q], rinv[b][c]
    combine_k<<<NB * (NQL + NCL) / 256, 256>>>(pLp, pRp, pinvl, prinv);

    // fork: y0 (Aᵀ path, independent of T) runs on s2 concurrently with K4
    cudaEventRecord(evF, 0);
    cudaStreamWaitEvent(s2, evF, 0);

    // y0 on s2: v = rinv*(Q @ E2^T) -> out[sec1]=v, out[sec2]=C*v
    mma_gemm<true, 2, 128, true, 2, 2><<<dim3(NCL / 128, 1, NB), 256, SM128, s2>>>(
        Q, nullptr, pE2, out, C, ND, NCL, NQL,
        (size_t)ND * NQL, (size_t)NCL * NQL, (size_t)4 * ND * NCL,
        prinv, nullptr, nullptr, 0);

    // K4 on main: T[d][q] = invl[q] * (C @ E2)   (M=D, N=QL, K=CL)
    mma_gemm<false, 2, 64, false, 4, 3><<<dim3(NQL / 64, 1, NB), 256, SM64>>>(
        C, nullptr, pE2, pT, nullptr, ND, NQL, NCL,
        (size_t)ND * NCL, (size_t)NCL * NQL, (size_t)ND * NQL,
        pinvl, nullptr, nullptr, 0);

    // y1 on main (after K4): v = rinv*(T @ E2^T) -> out[sec3]=C*v
    mma_gemm<true, 2, 128, true, 2, 2><<<dim3(NCL / 128, 1, NB), 256, SM128>>>(
        nullptr, pT, pE2, out, C, ND, NCL, NQL,
        (size_t)ND * NQL, (size_t)NCL * NQL, (size_t)4 * ND * NCL,
        prinv, nullptr, nullptr, 1);

    // join s2 back into the main stream
    cudaEventRecord(evJ, s2);
    cudaStreamWaitEvent(0, evJ, 0);
}

// round 15
// speedup vs baseline: 1.0410x; 1.0410x over previous
#include <cuda_runtime.h>
#include <cstdint>

#define NB  32
#define ND  128
#define NCL 1024
#define NQL 512

// ---------------- scratch (device globals: allocation-free) ----------------
__device__ float g_Aeff[(size_t)NB * NCL * ND];     // Aeff[b][c][d]
__device__ float g_bias[(size_t)NB * NCL];          // bias[b][c]
__device__ float g_E2 [(size_t)NB * NCL * NQL];     // exp(S+bias)  [b][c][q]
__device__ float g_Lp [(size_t)NB * 8 * NQL];       // column partial sums
__device__ float g_Rp [(size_t)NB * 4 * NCL];       // row partial sums
__device__ float g_invl[(size_t)NB * NQL];          // 1 / column sum
__device__ float g_rinv[(size_t)NB * NCL];          // 1 / row sum
__device__ float g_T  [(size_t)NB * ND * NQL];      // T[b][d][q] = S2tC^T

// ---------------- helpers ---------------------------------------------------
__device__ __forceinline__ void mma8(float* d, const uint32_t* a, const uint32_t* b) {
    asm("mma.sync.aligned.m16n8k8.row.col.f32.tf32.tf32.f32 "
        "{%0,%1,%2,%3}, {%4,%5,%6,%7}, {%8,%9}, {%0,%1,%2,%3};"
        : "+f"(d[0]), "+f"(d[1]), "+f"(d[2]), "+f"(d[3])
        : "r"(a[0]), "r"(a[1]), "r"(a[2]), "r"(a[3]), "r"(b[0]), "r"(b[1]));
}
__device__ __forceinline__ uint4 ldsm4(uint32_t addr) {
    uint4 r;
    asm volatile("ldmatrix.sync.aligned.m8n8.x4.shared.b16 {%0,%1,%2,%3}, [%4];"
                 : "=r"(r.x), "=r"(r.y), "=r"(r.z), "=r"(r.w) : "r"(addr));
    return r;
}
#define CP16(dst, src) \
    asm volatile("cp.async.cg.shared.global [%0], [%1], 16;" :: "r"(dst), "l"(src))
#define CPCOMMIT() asm volatile("cp.async.commit_group;" ::)
#define CPWAIT2()  asm volatile("cp.async.wait_group 2;" ::: "memory")

// ---------------- K0: Aeff = wq + wqc*Ct ; bias = wc . Ct ; out[sec0]=C -----
__global__ __launch_bounds__(256) void prep_kernel(
    const float* __restrict__ C, const float* __restrict__ W,
    float* __restrict__ Aeff, float* __restrict__ bias,
    float* __restrict__ out)
{
    __shared__ float Csm[ND][33];
    const int b  = blockIdx.y;
    const int c0 = blockIdx.x * 32;
    const int t  = threadIdx.x;
    const float* Cb = C + (size_t)b * ND * NCL;
    float* Ob = out + (size_t)b * 4 * ND * NCL;

    #pragma unroll
    for (int i = 0; i < 16; i++) {
        int idx = i * 256 + t;
        int d = idx >> 5, c = idx & 31;
        float v = Cb[(size_t)d * NCL + c0 + c];
        Csm[d][c] = v;
        Ob[(size_t)d * NCL + c0 + c] = v;   // out section 0 = C
    }
    __syncthreads();

    #pragma unroll
    for (int i = 0; i < 16; i++) {
        int idx = i * 256 + t;
        int c = idx >> 7, d = idx & 127;
        size_t wb = (size_t)(b * NCL + c0 + c) * 384;
        float wq  = W[wb + d];
        float wqc = W[wb + 256 + d];
        Aeff[(size_t)(b * NCL + c0 + c) * ND + d] = wq + wqc * Csm[d][c];
    }

    int w = t >> 5, lane = t & 31;
    #pragma unroll
    for (int j = 0; j < 4; j++) {
        int c = w + j * 8;
        size_t wb = (size_t)(b * NCL + c0 + c) * 384 + 128;
        float s = 0.f;
        #pragma unroll
        for (int jj = 0; jj < 4; jj++) {
            int d = lane + jj * 32;
            s += W[wb + d] * Csm[d][c];
        }
        #pragma unroll
        for (int off = 16; off; off >>= 1)
            s += __shfl_xor_sync(0xffffffffu, s, off);
        if (lane == 0) bias[b * NCL + c0 + c] = s;
    }
}

// ---------------- tf32 tensor-core GEMM: cp.async + ldmatrix pipeline --------
// 4-stage cp.async ring (3 tiles in flight), dynamic smem, swizzled tiles.
// Block tile BMT x BN; warp grid WM (m) x 8/WM (n).
// EPI=1: store exp(acc+bias[m]) + col/row partial sums (K1).
// EPI=2 & !MERGE: C = acc * xtra1[col]  (K4 -> T), m0 = blockIdx.y*BMT.
// EPI=2 & MERGE : fused final assembly (blockIdx.y: 0 -> sec1,sec2 ; 1 -> sec3).
template <bool TRANSB, int EPI, int BMT, int BN, bool MERGE, int WM, int OCC>
__global__ __launch_bounds__(256, OCC) void mma_gemm(
    const float* __restrict__ Aall, const float* __restrict__ Aall2,
    const float* __restrict__ Ball,
    float* __restrict__ Call, const float* __restrict__ Cprod,
    int M, int N, int K,
    size_t aStride, size_t bStride, size_t cStride,
    const float* __restrict__ xtra1,
    float* __restrict__ colpart, float* __restrict__ rowpart)
{
    constexpr int BM = BMT, BK = 16, STG = 4;
    constexpr int WN = 8 / WM;
    constexpr int MI = BM / (16 * WM);
    constexpr int NI = BN / (8 * WN);
    constexpr int ABYTES = BM * BK * 4;   // 8192 / 4096
    constexpr int BBYTES = BK * BN * 4;   // 8192 / 4096

    extern __shared__ float sdyn[];
    float* As = sdyn;                          // STG * BM*BK
    float* Bs = sdyn + STG * BM * BK;          // STG * BK*BN

    const int b  = blockIdx.z;
    const int n0 = blockIdx.x * BN;
    const int m0 = MERGE ? 0 : blockIdx.y * BM;
    const float* Abase = MERGE ? (blockIdx.y ? Aall2 : Aall) : Aall;
    const float* A  = Abase + (size_t)b * aStride + (size_t)m0 * K;
    const float* Bp = Ball + (size_t)b * bStride;
    float*       Cm = Call + (size_t)b * cStride;

    const int tid  = threadIdx.x;
    const int w    = tid >> 5;
    const int lane = tid & 31;
    const int g    = lane >> 2;
    const int t    = lane & 3;
    const int wq   = w / WN;                 // m-warp index
    const int wr   = w % WN;                 // n-warp index
    const int wm   = wq * (16 * MI);
    const int wn   = wr * (8 * NI);
    const int na0  = wr * NI;

    const uint32_t sAu = (uint32_t)__cvta_generic_to_shared(As);
    const uint32_t sBu = (uint32_t)__cvta_generic_to_shared(Bs);
    const int T = K / BK;

    // ---- global->smem loader setup (16B chunks, swizzled dst) ----
    const int rA = tid >> 2, cA = tid & 3;
    const float* gA0 = A + (size_t)rA * K + cA * 4;
    const float* gA1 = (BM == 128) ? gA0 + (size_t)64 * K : nullptr;
    const uint32_t dA0 = sAu + ((rA * 4 + (cA ^ ((rA >> 1) & 3))) << 4);
    const uint32_t dA1 = dA0 + 4096;

    const float* gB0;
    const float* gB1 = nullptr;
    uint32_t dB0, dB1 = 0;
    if (TRANSB) {
        const int rB = tid >> 2, cB = tid & 3;
        gB0 = Bp + (size_t)(n0 + rB) * K + cB * 4;
        dB0 = sBu + ((rB * 4 + (cB ^ ((rB >> 1) & 3))) << 4);
        if (BN == 128) { gB1 = gB0 + (size_t)64 * K; dB1 = dB0 + 4096; }
    } else {
        const int kB = tid >> 4, cB = tid & 15;
        gB0 = Bp + (size_t)kB * N + n0 + cB * 4;
        dB0 = sBu + ((kB * (BN / 4) + (cB ^ (2 * (kB & 3)))) << 4);
        if (BN == 128) { gB1 = gB0 + 64; dB1 = dB0 + 256; }
    }

    auto issue_tile = [&](int stage) {
        const uint32_t ao = stage * ABYTES, bo = stage * BBYTES;
        CP16(dA0 + ao, gA0);
        if (BM == 128) { CP16(dA1 + ao, gA1); gA1 += BK; }
        gA0 += BK;
        CP16(dB0 + bo, gB0);
        if (BN == 128) CP16(dB1 + bo, gB1);
        if (TRANSB) { gB0 += BK; if (BN == 128) gB1 += BK; }
        else        { gB0 += (size_t)BK * N; if (BN == 128) gB1 += (size_t)BK * N; }
    };

    // ---- fragment address precompute ----
    const int aRow = wm + ((lane >> 3) & 1) * 8 + (lane & 7);
    const int aSel = lane >> 4;
    const int fSwz = (lane >> 1) & 3;
    const int aB0  = aRow * 64;
    const int ax[2] = { ((aSel) ^ fSwz) << 4, ((2 + aSel) ^ fSwz) << 4 };

    int bRB[TRANSB ? (NI / 2) : 1];
    int bx0 = 0, bx1 = 0;
    if (TRANSB) {
        const int bSel = (lane >> 3) & 1;
        bx0 = ((bSel) ^ fSwz) << 4;
        bx1 = ((2 + bSel) ^ fSwz) << 4;
        #pragma unroll
        for (int p = 0; p < NI / 2; p++)
            bRB[p] = ((na0 + 2 * p + (lane >> 4)) * 8 + (lane & 7)) * 64;
    }
    int colB[TRANSB ? 1 : NI];
    int rw0 = 0, rw1 = 0;
    if (!TRANSB) {
        #pragma unroll
        for (int in = 0; in < NI; in++) {
            int cn = (wn >> 2) + in * 2 + (g >> 2);
            colB[in] = ((cn ^ (2 * t)) << 2) + (g & 3);
        }
        rw0 = t * BN;
        rw1 = (8 + t) * BN;
    }

    float acc[MI][NI][4];
    #pragma unroll
    for (int i = 0; i < MI; i++)
        #pragma unroll
        for (int j = 0; j < NI; j++)
            #pragma unroll
            for (int r = 0; r < 4; r++) acc[i][j][r] = 0.f;

    // ---- prologue: 3 stages in flight ----
    issue_tile(0); CPCOMMIT();
    issue_tile(1); CPCOMMIT();
    issue_tile(2); CPCOMMIT();

    for (int it = 0; it < T; ++it) {
        CPWAIT2();
        __syncthreads();
        if (it + 3 < T) issue_tile((it + 3) % STG);
        CPCOMMIT();

        const int st = it % STG;
        const uint32_t aSt = sAu + st * ABYTES;
        const uint32_t bSt = sBu + st * BBYTES;
        const uint32_t* Bw = (const uint32_t*)(Bs + st * BK * BN);

        #pragma unroll
        for (int ks = 0; ks < 2; ks++) {
            uint4 af[MI];
            #pragma unroll
            for (int im = 0; im < MI; im++)
                af[im] = ldsm4(aSt + aB0 + im * 1024 + ax[ks]);

            uint32_t bf[NI][2];
            if (TRANSB) {
                #pragma unroll
                for (int p = 0; p < NI / 2; p++) {
                    uint4 bv = ldsm4(bSt + bRB[p] + (ks ? bx1 : bx0));
                    bf[2 * p][0] = bv.x; bf[2 * p][1] = bv.y;
                    bf[2 * p + 1][0] = bv.z; bf[2 * p + 1][1] = bv.w;
                }
            } else {
                const int rw = ks ? rw1 : rw0;
                #pragma unroll
                for (int in = 0; in < NI; in++) {
                    bf[in][0] = Bw[rw + colB[in]];
                    bf[in][1] = Bw[rw + colB[in] + 4 * BN];
                }
            }
            #pragma unroll
            for (int im = 0; im < MI; im++)
                #pragma unroll
                for (int in = 0; in < NI; in++)
                    mma8(acc[im][in], (const uint32_t*)&af[im], bf[in]);
        }
    }

    // ---------------- epilogue ----------------
    if constexpr (EPI == 1) {
        float bias_r[MI][2];
        #pragma unroll
        for (int im = 0; im < MI; im++)
            #pragma unroll
            for (int h = 0; h < 2; h++)
                bias_r[im][h] = xtra1[(size_t)b * M + m0 + wm + im * 16 + g + 8 * h];

        float qs[NI][2];
        float rs[MI][2];
        #pragma unroll
        for (int i = 0; i < NI; i++) { qs[i][0] = 0.f; qs[i][1] = 0.f; }
        #pragma unroll
        for (int i = 0; i < MI; i++) { rs[i][0] = 0.f; rs[i][1] = 0.f; }

        #pragma unroll
        for (int im = 0; im < MI; im++)
            #pragma unroll
            for (int h = 0; h < 2; h++) {
                int m = m0 + wm + im * 16 + g + 8 * h;
                #pragma unroll
                for (int in = 0; in < NI; in++) {
                    float e0 = __expf(acc[im][in][2 * h]     + bias_r[im][h]);
                    float e1 = __expf(acc[im][in][2 * h + 1] + bias_r[im][h]);
                    float2 v; v.x = e0; v.y = e1;
                    *(float2*)&Cm[(size_t)m * N + n0 + wn + in * 8 + 2 * t] = v;
                    qs[in][0] += e0; qs[in][1] += e1;
                    rs[im][h] += e0 + e1;
                }
            }
        __syncthreads();
        float* red_c = sdyn;                 // [WM][BN]
        float* red_r = sdyn + WM * BN;       // [WN][BM]
        #pragma unroll
        for (int in = 0; in < NI; in++)
            #pragma unroll
            for (int j = 0; j < 2; j++) {
                float s = qs[in][j];
                s += __shfl_xor_sync(0xffffffffu, s, 16);
                s += __shfl_xor_sync(0xffffffffu, s, 8);
                s += __shfl_xor_sync(0xffffffffu, s, 4);
                if (g == 0) red_c[wq * BN + wn + in * 8 + 2 * t + j] = s;
            }
        #pragma unroll
        for (int im = 0; im < MI; im++)
            #pragma unroll
            for (int h = 0; h < 2; h++) {
                float s = rs[im][h];
                s += __shfl_xor_sync(0xffffffffu, s, 1);
                s += __shfl_xor_sync(0xffffffffu, s, 2);
                if (t == 0) red_r[wr * BM + wm + im * 16 + g + 8 * h] = s;
            }
        __syncthreads();
        if (tid < BN) {
            float s = 0.f;
            #pragma unroll
            for (int k2 = 0; k2 < WM; k2++) s += red_c[k2 * BN + tid];
            colpart[((size_t)b * gridDim.y + blockIdx.y) * N + n0 + tid] = s;
        } else if (tid < BN + BM) {
            int m = tid - BN;
            float s = 0.f;
            #pragma unroll
            for (int k2 = 0; k2 < WN; k2++) s += red_r[k2 * BM + m];
            rowpart[((size_t)b * gridDim.x + blockIdx.x) * M + m0 + m] = s;
        }
    } else {
        float sc[NI][2];
        #pragma unroll
        for (int in = 0; in < NI; in++)
            #pragma unroll
            for (int j = 0; j < 2; j++)
                sc[in][j] = xtra1[(size_t)b * N + n0 + wn + in * 8 + 2 * t + j];

        if constexpr (MERGE) {
            // fused assembly: Cm = out + b*4*ND*NCL
            const float* Cin = Cprod + (size_t)b * ND * NCL;
            const int yb = blockIdx.y;
            #pragma unroll
            for (int im = 0; im < MI; im++)
                #pragma unroll
                for (int h = 0; h < 2; h++) {
                    int m = wm + im * 16 + g + 8 * h;
                    #pragma unroll
                    for (int in = 0; in < NI; in++) {
                        int col = n0 + wn + in * 8 + 2 * t;
                        float2 v;
                        v.x = acc[im][in][2 * h]     * sc[in][0];
                        v.y = acc[im][in][2 * h + 1] * sc[in][1];
                        float2 cv = *(const float2*)&Cin[(size_t)m * NCL + col];
                        float2 p; p.x = cv.x * v.x; p.y = cv.y * v.y;
                        if (yb == 0) {
                            *(float2*)&Cm[(size_t)(ND + m) * NCL + col] = v;
                            *(float2*)&Cm[(size_t)(2 * ND + m) * NCL + col] = p;
                        } else {
                            *(float2*)&Cm[(size_t)(3 * ND + m) * NCL + col] = p;
                        }
                    }
                }
        } else {
            #pragma unroll
            for (int im = 0; im < MI; im++)
                #pragma unroll
                for (int h = 0; h < 2; h++) {
                    int m = m0 + wm + im * 16 + g + 8 * h;
                    #pragma unroll
                    for (int in = 0; in < NI; in++) {
                        float2 v;
                        v.x = acc[im][in][2 * h]     * sc[in][0];
                        v.y = acc[im][in][2 * h + 1] * sc[in][1];
                        *(float2*)&Cm[(size_t)m * N + n0 + wn + in * 8 + 2 * t] = v;
                    }
                }
        }
    }
}

// ---------------- combine partial sums -> invl (per q), rinv (per c) --------
__global__ __launch_bounds__(256) void combine_k(
    const float* __restrict__ Lp, const float* __restrict__ Rp,
    float* __restrict__ invl, float* __restrict__ rinv)
{
    int i = blockIdx.x * 256 + threadIdx.x;
    const int nbq = NB * NQL;
    if (i < nbq) {
        int b = i >> 9, q = i & 511;
        float s = 0.f;
        #pragma unroll
        for (int y = 0; y < 8; y++) s += Lp[((size_t)b * 8 + y) * NQL + q];
        invl[i] = 1.f / s;
    } else {
        int j = i - nbq;
        int b = j >> 10, c = j & 1023;
        float s = 0.f;
        #pragma unroll
        for (int x = 0; x < 4; x++) s += Rp[((size_t)b * 4 + x) * NCL + c];
        rinv[j] = 1.f / s;
    }
}

// ---------------- launch ----------------------------------------------------
extern "C" void kernel_launch(void* const* d_in, const int* in_sizes, int n_in,
                              void* d_out, int out_size)
{
    const float* C = (const float*)d_in[0];   // (B, D, CL)
    const float* Q = (const float*)d_in[1];   // (B, D, QL)
    const float* W = (const float*)d_in[2];   // (B*CL, 1, 3D)
    float* out = (float*)d_out;               // (B, 4D, CL)

    float *pAeff, *pbias, *pE2, *pLp, *pRp, *pinvl, *prinv, *pT;
    cudaGetSymbolAddress((void**)&pAeff, g_Aeff);
    cudaGetSymbolAddress((void**)&pbias, g_bias);
    cudaGetSymbolAddress((void**)&pE2,   g_E2);
    cudaGetSymbolAddress((void**)&pLp,   g_Lp);
    cudaGetSymbolAddress((void**)&pRp,   g_Rp);
    cudaGetSymbolAddress((void**)&pinvl, g_invl);
    cudaGetSymbolAddress((void**)&prinv, g_rinv);
    cudaGetSymbolAddress((void**)&pT,    g_T);

    // dynamic smem sizes: STG=4 stages
    const int SM128 = 4 * (8192 + 8192);   // 64 KB  (BM=128, BN=128)
    const int SM64  = 4 * (4096 + 4096);   // 32 KB  (BM=64,  BN=64)
    cudaFuncSetAttribute(mma_gemm<false, 1, 128, 128, false, 2, 2>,
                         cudaFuncAttributeMaxDynamicSharedMemorySize, SM128);
    cudaFuncSetAttribute(mma_gemm<false, 2, 64, 64, false, 2, 4>,
                         cudaFuncAttributeMaxDynamicSharedMemorySize, SM64);
    cudaFuncSetAttribute(mma_gemm<true, 2, 128, 128, true, 2, 2>,
                         cudaFuncAttributeMaxDynamicSharedMemorySize, SM128);

    // K0: Aeff + bias + out[sec0] = C
    prep_kernel<<<dim3(NCL / 32, NB), 256>>>(C, W, pAeff, pbias, out);

    // K1: E2 = exp(Aeff @ Q + bias[c]); column+row partial sums
    mma_gemm<false, 1, 128, 128, false, 2, 2><<<dim3(NQL / 128, NCL / 128, NB), 256, SM128>>>(
        pAeff, nullptr, Q, pE2, nullptr, NCL, NQL, ND,
        (size_t)NCL * ND, (size_t)ND * NQL, (size_t)NCL * NQL,
        pbias, pLp, pRp);

    // combine -> invl[b][q], rinv[b][c]
    combine_k<<<NB * (NQL + NCL) / 256, 256>>>(pLp, pRp, pinvl, prinv);

    // K4: T[d][q] = invl[q] * (C @ E2)   (M=D, N=QL, K=CL)
    //     BM=64 x BN=64, grid (8, 2, 32) = 512 blocks @ OCC=4 -> one full wave
    mma_gemm<false, 2, 64, 64, false, 2, 4><<<dim3(NQL / 64, ND / 64, NB), 256, SM64>>>(
        C, nullptr, pE2, pT, nullptr, ND, NQL, NCL,
        (size_t)ND * NCL, (size_t)NCL * NQL, (size_t)ND * NQL,
        pinvl, nullptr, nullptr);

    // K3+K5 merged + fused assembly (single launch: L2-shares E2 across y):
    //   y=0: v = rinv*(Q @ E2^T) -> out[sec1]=v, out[sec2]=C*v
    //   y=1: v = rinv*(T @ E2^T) -> out[sec3]=C*v
    mma_gemm<true, 2, 128, 128, true, 2, 2><<<dim3(NCL / 128, 2, NB), 256, SM128>>>(
        Q, pT, pE2, out, C, ND, NCL, NQL,
        (size_t)ND * NQL, (size_t)NCL * NQL, (size_t)4 * ND * NCL,
        prinv, nullptr, nullptr);
}